// round 4
// baseline (speedup 1.0000x reference)
#include <cuda_runtime.h>

#define N_COLS  22
#define N_PAIRS 231
#define EMB_NUM 12
#define DIM     64
#define BATCH   4096
#define NFF     (EMB_NUM * EMB_NUM)   // 144

// Precomputed pair-contribution table: T[p][fi][fj] -> (out0, out1)
__device__ float2 g_T[N_PAIRS * NFF];
__device__ int    g_ij[N_PAIRS];

// One CTA per pair. Stage alpha-folded weights + candidate table rows in smem,
// then 8 warps sweep the 144 (fi,fj) combos.
__global__ __launch_bounds__(256) void nasp_prep_kernel(
        const float* __restrict__ tables,
        const float* __restrict__ Ws,   // (231,4,2,64)
        const float* __restrict__ Wc,   // (231,2,128)
        const float* __restrict__ aw) { // (231,5)
    __shared__ float sA[8][DIM];        // a_k * W_small[p][k][o][d], row = k*2+o
    __shared__ float sC[4][DIM];        // a_4 * W_concat[p][o][half*64+d], row = o*2+half
    __shared__ float sP[EMB_NUM][DIM];  // tables[i][*][:]
    __shared__ float sQ[EMB_NUM][DIM];  // tables[j][*][:]

    int p   = blockIdx.x;
    int tid = threadIdx.x;

    // triu_indices(22, k=1) row-major unrank
    int i = 0, rem = p, span = N_COLS - 1;
    while (rem >= span) { rem -= span; i++; span--; }
    int j = i + 1 + rem;

    // Stage weights with arch_weights folded in
    for (int idx = tid; idx < 512; idx += 256) {
        int k = idx >> 7;                              // layout [k][o][d]
        sA[idx >> 6][idx & 63] = Ws[p * 512 + idx] * aw[p * 5 + k];
    }
    {
        float a4 = aw[p * 5 + 4];
        int idx = tid;                                 // exactly 256 elems
        sC[idx >> 6][idx & 63] = Wc[p * 256 + idx] * a4;
    }
    // Stage all 12 candidate rows for columns i and j (768 floats each)
    for (int idx = tid; idx < EMB_NUM * DIM; idx += 256) {
        sP[idx >> 6][idx & 63] = tables[(i * EMB_NUM) * DIM + idx];
        sQ[idx >> 6][idx & 63] = tables[(j * EMB_NUM) * DIM + idx];
    }
    if (tid == 0) g_ij[p] = (i << 5) | j;
    __syncthreads();

    int warp = tid >> 5, lane = tid & 31;
    for (int c = warp; c < NFF; c += 8) {
        int fi = c / EMB_NUM;
        int fj = c - fi * EMB_NUM;
        float acc0 = 0.f, acc1 = 0.f;
#pragma unroll
        for (int r = 0; r < 2; r++) {
            int d = lane + 32 * r;
            float P = sP[fi][d], Q = sQ[fj][d];
            float s  = P + Q;
            float m  = P * Q;
            float mx = fmaxf(P, Q);
            float mn = fminf(P, Q);
            acc0 += s * sA[0][d] + m * sA[2][d] + mx * sA[4][d] + mn * sA[6][d]
                  + P * sC[0][d] + Q * sC[1][d];
            acc1 += s * sA[1][d] + m * sA[3][d] + mx * sA[5][d] + mn * sA[7][d]
                  + P * sC[2][d] + Q * sC[3][d];
        }
#pragma unroll
        for (int off = 16; off; off >>= 1) {
            acc0 += __shfl_xor_sync(0xffffffffu, acc0, off);
            acc1 += __shfl_xor_sync(0xffffffffu, acc1, off);
        }
        if (lane == 0) g_T[p * NFF + c] = make_float2(acc0, acc1);
    }
}

// One warp per batch row: sum 231 table lookups (g_T is L2-resident, 266 KB).
__global__ __launch_bounds__(256) void nasp_main_kernel(
        const int* __restrict__ feats,
        float* __restrict__ out) {
    __shared__ int s_ij[256];                     // padded copy of g_ij
    {
        int t = threadIdx.x;
        s_ij[t] = (t < N_PAIRS) ? g_ij[t] : 33;   // dummy (i=1,j=1)
    }
    __syncthreads();

    int gw   = (blockIdx.x * blockDim.x + threadIdx.x) >> 5;
    int lane = threadIdx.x & 31;
    if (gw >= BATCH) return;
    int b = gw;
    int f = (lane < N_COLS) ? feats[b * N_COLS + lane] : 0;

    // Hoist this lane's 8 pair descriptors to registers up front.
    int ijr[8];
#pragma unroll
    for (int t = 0; t < 8; t++) {
        int p = lane + 32 * t;
        ijr[t] = s_ij[p < N_PAIRS ? p : N_PAIRS];  // p>=231 -> dummy slot
    }

    // 8 independent (shfl,shfl,ldg) chains -> ptxas can front-batch the loads.
    float2 v[8];
#pragma unroll
    for (int t = 0; t < 8; t++) {
        int p  = lane + 32 * t;
        int i  = ijr[t] >> 5, j = ijr[t] & 31;
        int fi = __shfl_sync(0xffffffffu, f, i);
        int fj = __shfl_sync(0xffffffffu, f, j);
        v[t] = (p < N_PAIRS) ? __ldg(&g_T[p * NFF + fi * EMB_NUM + fj])
                             : make_float2(0.f, 0.f);
    }

    float acc0 = 0.f, acc1 = 0.f;
#pragma unroll
    for (int t = 0; t < 8; t++) { acc0 += v[t].x; acc1 += v[t].y; }

#pragma unroll
    for (int off = 16; off; off >>= 1) {
        acc0 += __shfl_xor_sync(0xffffffffu, acc0, off);
        acc1 += __shfl_xor_sync(0xffffffffu, acc1, off);
    }
    if (lane == 0) {
        out[2 * b + 0] = acc0;
        out[2 * b + 1] = acc1;
    }
}

extern "C" void kernel_launch(void* const* d_in, const int* in_sizes, int n_in,
                              void* d_out, int out_size) {
    const int*   feats  = (const int*)  d_in[0];
    const float* tables = (const float*)d_in[1];
    const float* Ws     = (const float*)d_in[2];
    const float* Wc     = (const float*)d_in[3];
    const float* aw     = (const float*)d_in[4];
    float* out = (float*)d_out;

    nasp_prep_kernel<<<N_PAIRS, 256>>>(tables, Ws, Wc, aw);

    int threads = 256;
    int blocks  = (BATCH * 32 + threads - 1) / threads;
    nasp_main_kernel<<<blocks, threads>>>(feats, out);
}

// round 5
// speedup vs baseline: 1.8790x; 1.8790x over previous
#include <cuda_runtime.h>

#define N_COLS    22
#define N_PAIRS   231
#define EMB_NUM   12
#define DIM       64
#define BATCH     4096
#define NFF       (EMB_NUM * EMB_NUM)   // 144
#define ROWS_TILE 32
#define MAIN_WARPS 16
#define MAIN_ITERS 15                   // ceil(231/16)

// Precomputed pair-contribution table: T[p][fi][fj] -> (out0, out1)
__device__ float2 g_T[N_PAIRS * NFF];
__device__ int    g_ij[N_PAIRS];

// One CTA per pair. Stage alpha-folded weights + candidate table rows in smem,
// then 8 warps sweep the 144 (fi,fj) combos.
__global__ __launch_bounds__(256) void nasp_prep_kernel(
        const float* __restrict__ tables,
        const float* __restrict__ Ws,   // (231,4,2,64)
        const float* __restrict__ Wc,   // (231,2,128)
        const float* __restrict__ aw) { // (231,5)
    __shared__ float sA[8][DIM];        // a_k * W_small[p][k][o][d], row = k*2+o
    __shared__ float sC[4][DIM];        // a_4 * W_concat[p][o][half*64+d], row = o*2+half
    __shared__ float sP[EMB_NUM][DIM];  // tables[i][*][:]
    __shared__ float sQ[EMB_NUM][DIM];  // tables[j][*][:]

    int p   = blockIdx.x;
    int tid = threadIdx.x;

    // triu_indices(22, k=1) row-major unrank
    int i = 0, rem = p, span = N_COLS - 1;
    while (rem >= span) { rem -= span; i++; span--; }
    int j = i + 1 + rem;

    for (int idx = tid; idx < 512; idx += 256) {
        int k = idx >> 7;                              // layout [k][o][d]
        sA[idx >> 6][idx & 63] = Ws[p * 512 + idx] * aw[p * 5 + k];
    }
    {
        float a4 = aw[p * 5 + 4];
        int idx = tid;                                 // exactly 256 elems
        sC[idx >> 6][idx & 63] = Wc[p * 256 + idx] * a4;
    }
    for (int idx = tid; idx < EMB_NUM * DIM; idx += 256) {
        sP[idx >> 6][idx & 63] = tables[(i * EMB_NUM) * DIM + idx];
        sQ[idx >> 6][idx & 63] = tables[(j * EMB_NUM) * DIM + idx];
    }
    if (tid == 0) g_ij[p] = (i << 5) | j;
    __syncthreads();

    int warp = tid >> 5, lane = tid & 31;
    for (int c = warp; c < NFF; c += 8) {
        int fi = c / EMB_NUM;
        int fj = c - fi * EMB_NUM;
        float acc0 = 0.f, acc1 = 0.f;
#pragma unroll
        for (int r = 0; r < 2; r++) {
            int d = lane + 32 * r;
            float P = sP[fi][d], Q = sQ[fj][d];
            float s  = P + Q;
            float m  = P * Q;
            float mx = fmaxf(P, Q);
            float mn = fminf(P, Q);
            acc0 += s * sA[0][d] + m * sA[2][d] + mx * sA[4][d] + mn * sA[6][d]
                  + P * sC[0][d] + Q * sC[1][d];
            acc1 += s * sA[1][d] + m * sA[3][d] + mx * sA[5][d] + mn * sA[7][d]
                  + P * sC[2][d] + Q * sC[3][d];
        }
#pragma unroll
        for (int off = 16; off; off >>= 1) {
            acc0 += __shfl_xor_sync(0xffffffffu, acc0, off);
            acc1 += __shfl_xor_sync(0xffffffffu, acc1, off);
        }
        if (lane == 0) g_T[p * NFF + c] = make_float2(acc0, acc1);
    }
}

// CTA = 32-row tile, 16 warps. Lane = row, warp = pair-subset.
// Each gather LDG stays inside one pair's 1152B slab -> ~9 wavefronts, not 32.
__global__ __launch_bounds__(512) void nasp_main_kernel(
        const int* __restrict__ feats,
        float* __restrict__ out) {
    __shared__ int    s_feat[N_COLS][ROWS_TILE];     // transposed feat tile
    __shared__ int    s_ij[N_PAIRS];
    __shared__ float2 s_part[MAIN_WARPS][ROWS_TILE]; // per-warp partials

    int tid  = threadIdx.x;
    int base = blockIdx.x * ROWS_TILE;

    for (int idx = tid; idx < ROWS_TILE * N_COLS; idx += 512) {
        int r = idx / N_COLS, c = idx - r * N_COLS;
        s_feat[c][r] = feats[(base + r) * N_COLS + c];
    }
    if (tid < N_PAIRS) s_ij[tid] = g_ij[tid];
    __syncthreads();

    int w = tid >> 5, l = tid & 31;   // l = row within tile
    float a0 = 0.f, a1 = 0.f;
#pragma unroll
    for (int t = 0; t < MAIN_ITERS; t++) {
        int p = w + MAIN_WARPS * t;
        if (p < N_PAIRS) {
            int ij = s_ij[p];                 // uniform across warp -> broadcast
            int fi = s_feat[ij >> 5][l];      // conflict-free LDS
            int fj = s_feat[ij & 31][l];
            float2 v = __ldg(&g_T[p * NFF + fi * EMB_NUM + fj]);
            a0 += v.x;
            a1 += v.y;
        }
    }
    s_part[w][l] = make_float2(a0, a1);
    __syncthreads();

    // 64 threads: thread t -> (row, out-component)
    if (tid < ROWS_TILE * 2) {
        int r = tid >> 1, o = tid & 1;
        float s = 0.f;
#pragma unroll
        for (int ww = 0; ww < MAIN_WARPS; ww++)
            s += o ? s_part[ww][r].y : s_part[ww][r].x;
        out[(base + r) * 2 + o] = s;
    }
}

extern "C" void kernel_launch(void* const* d_in, const int* in_sizes, int n_in,
                              void* d_out, int out_size) {
    const int*   feats  = (const int*)  d_in[0];
    const float* tables = (const float*)d_in[1];
    const float* Ws     = (const float*)d_in[2];
    const float* Wc     = (const float*)d_in[3];
    const float* aw     = (const float*)d_in[4];
    float* out = (float*)d_out;

    nasp_prep_kernel<<<N_PAIRS, 256>>>(tables, Ws, Wc, aw);
    nasp_main_kernel<<<BATCH / ROWS_TILE, 512>>>(feats, out);
}